// round 16
// baseline (speedup 1.0000x reference)
#include <cuda_runtime.h>
#include <cuda_fp16.h>
#include <math.h>

#define B_ 256
#define T_ 512
#define N_ 512
#define H_ 256

typedef unsigned long long u64;
typedef unsigned u32;

// ---------------- scratch (device globals; allocation-free) ----------------
__device__ u32   g_Eh[(size_t)B_ * N_ * 64];    // E half2, h<128   [b][n][h2]
__device__ u32   g_Qh[(size_t)T_ * B_ * 64];    // Q half2, h<128   [t][b][h2]
__device__ float g_Ea[(size_t)B_ * N_ * 128];   // e^{2E}, h>=128   [b][n][hc]
__device__ float g_Qa[(size_t)T_ * B_ * 128];   // e^{2Q}, h>=128   [t][b][hc]
__device__ u32   g_Hallh[(size_t)T_ * B_ * 128];// hiddens half2 [t][b][h2]
__device__ u32   g_hidh[2][B_ * 128];           // double-buffered hid half2
__device__ unsigned g_barcnt[16 * 32];          // 128B-padded barriers

// ---------------- fast-math helpers ----------------
__device__ __forceinline__ float tanha(float x) {
    float y; asm("tanh.approx.f32 %0, %1;" : "=f"(y) : "f"(x)); return y;
}
__device__ __forceinline__ float sigma_(float x) {
    return fmaf(0.5f, tanha(0.5f * x), 0.5f);
}
__device__ __forceinline__ u64 ffma2(u64 a, u64 b, u64 c) {
    u64 r; asm("fma.rn.f32x2 %0, %1, %2, %3;" : "=l"(r) : "l"(a), "l"(b), "l"(c));
    return r;
}
__device__ __forceinline__ u64 fmul2(u64 a, u64 b) {
    u64 r; asm("mul.rn.f32x2 %0, %1, %2;" : "=l"(r) : "l"(a), "l"(b));
    return r;
}
__device__ __forceinline__ u64 fdup2(float x) {
    u64 r; asm("mov.b64 %0, {%1, %1};" : "=l"(r) : "f"(x)); return r;
}
__device__ __forceinline__ float fsum2(u64 a) {
    float lo, hi; asm("mov.b64 {%0, %1}, %2;" : "=f"(lo), "=f"(hi) : "l"(a));
    return lo + hi;
}
__device__ __forceinline__ u32 packh2(float a, float b) {
    __half2 h = __floats2half2_rn(a, b);
    return *reinterpret_cast<u32*>(&h);
}
// half(low 16 bits) -> float, pure ALU (exact for normals)
__device__ __forceinline__ float h2f_fast(u32 hb) {
    u32 r = ((hb & 0x8000u) << 16) + ((hb & 0x7FFFu) << 13) + 0x38000000u;
    return __uint_as_float(r);
}
// packed Newton reciprocal: returns z2 = -1/u (rel err ~1e-5), u > 0 per lane
__device__ __forceinline__ u64 rcp_negz(u64 u, u64 M2, u64 P2c) {
    u32 lo, hi;
    asm("mov.b64 {%0, %1}, %2;" : "=r"(lo), "=r"(hi) : "l"(u));
    lo = 0x7EF127EAu - lo;
    hi = 0x7EF127EAu - hi;
    u64 y0;
    asm("mov.b64 %0, {%1, %2};" : "=l"(y0) : "r"(lo), "r"(hi));
    u64 t1 = ffma2(u, y0, M2);   // u*y0 - 2
    u64 z1 = fmul2(y0, t1);      // -y1
    u64 t2 = ffma2(u, z1, P2c);  // 2 + u*z1
    return fmul2(z1, t2);        // -y2  (y2 ~= 1/u)
}
__device__ __forceinline__ u32 smem_u32(const void* p) {
    u32 a;
    asm("{ .reg .u64 t; cvta.to.shared.u64 t, %1; cvt.u32.u64 %0, t; }"
        : "=r"(a) : "l"(p));
    return a;
}

#define LDSM4(a, addr)                                                   \
    asm volatile("ldmatrix.sync.aligned.m8n8.x4.shared.b16 "             \
                 "{%0,%1,%2,%3}, [%4];"                                  \
                 : "=r"((a)[0]), "=r"((a)[1]), "=r"((a)[2]), "=r"((a)[3])\
                 : "r"(addr))

#define MMA16816(d, a, b0, b1)                                           \
    asm volatile("mma.sync.aligned.m16n8k16.row.col.f32.f16.f16.f32 "    \
                 "{%0,%1,%2,%3}, {%4,%5,%6,%7}, {%8,%9}, {%0,%1,%2,%3};" \
                 : "+f"((d)[0]), "+f"((d)[1]), "+f"((d)[2]), "+f"((d)[3])\
                 : "r"((a)[0]), "r"((a)[1]), "r"((a)[2]), "r"((a)[3]),   \
                   "r"(b0), "r"(b1))

// ---------------------------------------------------------------------------
// Tensor-core GEMM (R12, proven): Out[m][k] = sum_h X[m][h] * W[k][h]
// Block (0,0,0) zeroes scan barrier counters.
// ---------------------------------------------------------------------------
#define GXP 264
#define GWP 264
#define GEMM_SMEM (64 * GXP * 2 + 128 * GWP * 2)

__global__ __launch_bounds__(256) void gemm_kernel(
    const void* __restrict__ Xin, const float* __restrict__ W,
    u32* __restrict__ OutH, float* __restrict__ OutA, int xf16) {
    extern __shared__ char gsm[];
    __half* Xh = (__half*)gsm;          // [64][GXP]
    __half* Wh = Xh + 64 * GXP;         // [128][GWP]
    const int tid = threadIdx.x;
    if (blockIdx.x == 0 && blockIdx.y == 0 && tid < 16) g_barcnt[tid * 32] = 0u;

    const size_t m0 = (size_t)blockIdx.x * 64;
    const int k0 = blockIdx.y * 128;

    if (xf16) {
        const uint4* xp = (const uint4*)((const __half*)Xin + m0 * H_);
        for (int i = tid; i < 2048; i += 256) {
            uint4 v = __ldg(xp + i);
            int row = i >> 5, c8 = i & 31;
            u32* d = (u32*)Xh + row * (GXP / 2) + c8 * 4;
            d[0] = v.x; d[1] = v.y; d[2] = v.z; d[3] = v.w;
        }
    } else {
        const float4* xp = (const float4*)((const float*)Xin + m0 * H_);
        for (int i = tid; i < 4096; i += 256) {
            float4 v = __ldg(xp + i);
            int row = i >> 6, c4 = i & 63;
            u32* d = (u32*)Xh + row * (GXP / 2) + c4 * 2;
            d[0] = packh2(v.x, v.y);
            d[1] = packh2(v.z, v.w);
        }
    }
    {
        const float4* wp = (const float4*)(W + (size_t)k0 * H_);
        for (int i = tid; i < 8192; i += 256) {
            float4 v = __ldg(wp + i);
            int row = i >> 6, c4 = i & 63;
            u32* d = (u32*)Wh + row * (GWP / 2) + c4 * 2;
            d[0] = packh2(v.x, v.y);
            d[1] = packh2(v.z, v.w);
        }
    }
    __syncthreads();

    const int w = tid >> 5, lane = tid & 31;
    u32 breg[16][2][2];
#pragma unroll
    for (int kk = 0; kk < 16; kk++)
#pragma unroll
        for (int nn = 0; nn < 2; nn++) {
            int row = w * 16 + nn * 8 + (lane >> 2);
            int h0 = kk * 16 + (lane & 3) * 2;
            breg[kk][nn][0] = *(const u32*)&Wh[row * GWP + h0];
            breg[kk][nn][1] = *(const u32*)&Wh[row * GWP + h0 + 8];
        }

    const u32 ldb = smem_u32(Xh) +
                    (u32)(((lane & 15) * GXP + ((lane >> 4) << 3)) * 2);
    float c[4][2][4];
#pragma unroll
    for (int mi = 0; mi < 4; mi++)
#pragma unroll
        for (int nn = 0; nn < 2; nn++)
#pragma unroll
            for (int q = 0; q < 4; q++) c[mi][nn][q] = 0.f;

#pragma unroll
    for (int kk = 0; kk < 16; kk++) {
#pragma unroll
        for (int mi = 0; mi < 4; mi++) {
            u32 a[4];
            LDSM4(a, ldb + (u32)((mi * 16 * GXP + kk * 16) * 2));
            MMA16816(c[mi][0], a, breg[kk][0][0], breg[kk][0][1]);
            MMA16816(c[mi][1], a, breg[kk][1][0], breg[kk][1][1]);
        }
    }

    const int qr = lane >> 2, qc = (lane & 3) * 2;
    if (k0 == 0) {
#pragma unroll
        for (int mi = 0; mi < 4; mi++)
#pragma unroll
            for (int nn = 0; nn < 2; nn++) {
                size_t m = m0 + mi * 16 + qr;
                int widx = w * 8 + nn * 4 + (lane & 3);
                OutH[m * 64 + widx] = packh2(c[mi][nn][0], c[mi][nn][1]);
                OutH[(m + 8) * 64 + widx] = packh2(c[mi][nn][2], c[mi][nn][3]);
            }
    } else {
#pragma unroll
        for (int mi = 0; mi < 4; mi++)
#pragma unroll
            for (int nn = 0; nn < 2; nn++) {
                size_t m = m0 + mi * 16 + qr;
                int col = w * 16 + nn * 8 + qc;
                *(float2*)&OutA[m * 128 + col] =
                    make_float2(__expf(2.f * c[mi][nn][0]),
                                __expf(2.f * c[mi][nn][1]));
                *(float2*)&OutA[(m + 8) * 128 + col] =
                    make_float2(__expf(2.f * c[mi][nn][2]),
                                __expf(2.f * c[mi][nn][3]));
            }
    }
}

// ---------------------------------------------------------------------------
// LSTM scan, 4-CTA groups: 16 groups x 4 CTAs (64 CTAs, 1/SM), 512 threads.
// CTA j of a group owns 64 h-cols; weights 256x256 fp16 (135KB) smem-resident.
// Per step: gates[16 bat][256 gr] via HMMA (16 warps x 16 n-cols, stationary
// B-frags); update 2 h-cols/thread; 4-arrival L2 barrier; 8KB hid reload.
// ---------------------------------------------------------------------------
#define WPAD 264
#define HPAD 264
#define PST 264
#define SCAN_SMEM (256 * WPAD * 2 + 16 * HPAD * 2 + 16 * PST * 4 + 256 * 4)

__global__ __launch_bounds__(512) void scan_kernel(
    const float* __restrict__ W_ih, const float* __restrict__ W_hh,
    const float* __restrict__ b_ih, const float* __restrict__ b_hh) {
    extern __shared__ char smc[];
    __half* Wh  = (__half*)smc;                    // [256][WPAD] fp16 weights
    __half* hidh = Wh + 256 * WPAD;                // [16][HPAD] fp16 hid
    float* P   = (float*)(hidh + 16 * HPAD);       // [16][PST] gates f32
    float* bcs = P + 16 * PST;                     // [256]

    const int tid = threadIdx.x;
    const int grp = blockIdx.x >> 2, j = blockIdx.x & 3;
    const int r0 = grp * 16, hbase = j * 64;
    const int w = tid >> 5, lane = tid & 31;

    // ---- load combined weights as fp16: local gate-col q -> global row ----
    for (int idx = tid; idx < 256 * 256; idx += 512) {
        int q = idx >> 8, h = idx & 255;              // q = gt*64 + hcol
        int row = (q >> 6) * 256 + hbase + (q & 63);
        size_t ww = (size_t)row * H_ + h;
        Wh[q * WPAD + h] = __float2half(W_ih[ww] + W_hh[ww]);
    }
    if (tid < 256) {
        int row = (tid >> 6) * 256 + hbase + (tid & 63);
        bcs[tid] = b_ih[row] + b_hh[row];
    }
    // hid starts at zero (single launch covers all 512 steps)
    for (int i2 = tid; i2 < 16 * (HPAD / 2); i2 += 512)
        ((u32*)hidh)[i2] = 0u;
    const int hc = tid & 31, bat = tid >> 5;   // update: bat x cols {2hc,2hc+1}
    float cell[2] = {0.f, 0.f};
    __syncthreads();

    // ---- hoist stationary B fragments: warp w -> local cols [16w,16w+16) ----
    u32 breg[16][2][2];
#pragma unroll
    for (int kk = 0; kk < 16; kk++)
#pragma unroll
        for (int nn = 0; nn < 2; nn++) {
            int row = w * 16 + nn * 8 + (lane >> 2);
            int h0 = kk * 16 + (lane & 3) * 2;
            breg[kk][nn][0] = *(const u32*)&Wh[row * WPAD + h0];
            breg[kk][nn][1] = *(const u32*)&Wh[row * WPAD + h0 + 8];
        }

    const u32 ld_base = smem_u32(hidh) +
                        (u32)(((lane & 15) * HPAD + ((lane >> 4) << 3)) * 2);
    const int qr = lane >> 2, qc = (lane & 3) * 2;
    unsigned* barp = &g_barcnt[grp * 32];

    for (int t = 0; t < T_; t++) {
        float c0[4] = {0.f, 0.f, 0.f, 0.f};
        float c1[4] = {0.f, 0.f, 0.f, 0.f};
#pragma unroll
        for (int kk = 0; kk < 16; kk++) {
            u32 a[4];
            LDSM4(a, ld_base + (u32)(kk * 32));
            MMA16816(c0, a, breg[kk][0][0], breg[kk][0][1]);
            MMA16816(c1, a, breg[kk][1][0], breg[kk][1][1]);
        }
        {
            int col = w * 16 + qc;
            *(float2*)&P[qr * PST + col] = make_float2(c0[0], c0[1]);
            *(float2*)&P[(qr + 8) * PST + col] = make_float2(c0[2], c0[3]);
            *(float2*)&P[qr * PST + col + 8] = make_float2(c1[0], c1[1]);
            *(float2*)&P[(qr + 8) * PST + col + 8] = make_float2(c1[2], c1[3]);
        }
        __syncthreads();

        // ---- LSTM update: thread -> bat x cols (2hc, 2hc+1); gates at
        //      local offsets {0,64,128,192} (i,f,g,o x 64 h-cols) ----
        const int buf = (t + 1) & 1;
        {
            const float* pp = &P[bat * PST];
            float2 iv = *(const float2*)&pp[2 * hc];
            float2 fv = *(const float2*)&pp[64 + 2 * hc];
            float2 gv = *(const float2*)&pp[128 + 2 * hc];
            float2 ov = *(const float2*)&pp[192 + 2 * hc];
            float2 bi = *(const float2*)&bcs[2 * hc];
            float2 bf = *(const float2*)&bcs[64 + 2 * hc];
            float2 bg = *(const float2*)&bcs[128 + 2 * hc];
            float2 bo = *(const float2*)&bcs[192 + 2 * hc];
            cell[0] = sigma_(fv.x + bf.x) * cell[0] +
                      sigma_(iv.x + bi.x) * tanha(gv.x + bg.x);
            cell[1] = sigma_(fv.y + bf.y) * cell[1] +
                      sigma_(iv.y + bi.y) * tanha(gv.y + bg.y);
            float hd0 = sigma_(ov.x + bo.x) * tanha(cell[0]);
            float hd1 = sigma_(ov.y + bo.y) * tanha(cell[1]);
            u32 h2 = packh2(hd0, hd1);
            g_hidh[buf][(r0 + bat) * 128 + (hbase >> 1) + hc] = h2;
            g_Hallh[((size_t)t * B_ + r0 + bat) * 128 + (hbase >> 1) + hc] = h2;
        }

        // ---- group barrier (4 CTAs): release arrive, acquire poll ----
        __syncthreads();
        if (tid == 0) {
            asm volatile("red.release.gpu.global.add.u32 [%0], %1;"
                         :: "l"(barp), "r"(1u) : "memory");
            unsigned tgt = (unsigned)(t + 1) * 4u, cur;
            do {
                asm volatile("ld.acquire.gpu.global.u32 %0, [%1];"
                             : "=r"(cur) : "l"(barp) : "memory");
            } while (cur < tgt);
        }
        __syncthreads();

        // ---- reload group's 16 hid rows (1 uint4 per thread) ----
        {
            const uint4* src = (const uint4*)&g_hidh[buf][r0 * 128];
            uint4 v = __ldcg(src + tid);
            int bb = tid >> 5, c8 = tid & 31;
            u32* d = (u32*)hidh + bb * (HPAD / 2) + c8 * 4;
            d[0] = v.x; d[1] = v.y; d[2] = v.z; d[3] = v.w;
        }
        __syncthreads();
    }
}

// ---------------------------------------------------------------------------
// Attention hybrid (R12 form, proven fastest — FROZEN):
//   phase 1 (h<128):  HADD2 -> tanh.f16x2 (MUFU) -> HFMA2 -> ALU widen
//   phase 2 (h>=128): tanh = 1 - 2/(1+ab), Newton rcp on FMA pipe
// ---------------------------------------------------------------------------
#define HSTR 68
#define ASTR 132
#define ATTN_SMEM (2 * 64 * HSTR * 4 + 2 * 64 * ASTR * 4 + 64 * 4 + 64 * 8)

#define HADD2A(r, a, b) asm("add.rn.f16x2 %0, %1, %2;" : "=r"(r) : "r"(a), "r"(b))
#define TANH2A(r, a)    asm("tanh.approx.f16x2 %0, %1;" : "=r"(r) : "r"(a))
#define HFMA2A(d, a, b) asm("fma.rn.f16x2 %0, %1, %2, %3;" : "=r"(d) : "r"(a), "r"(b), "r"(d))

#define ATC(accr, qc, ec, vc)            \
    { u32 s_, t_;                        \
      HADD2A(s_, (qc), (ec));            \
      TANH2A(t_, s_);                    \
      HFMA2A((accr), (vc), t_); }

#define AT4H(accr, q4, e4, v4)           \
    ATC(accr, (q4).x, (e4).x, (v4).x);   \
    ATC(accr, (q4).y, (e4).y, (v4).y);   \
    ATC(accr, (q4).z, (e4).z, (v4).z);   \
    ATC(accr, (q4).w, (e4).w, (v4).w)

__global__ __launch_bounds__(256) void attn_kernel(
    const float* __restrict__ v, float* __restrict__ out) {
    extern __shared__ u32 smu[];
    u32* Qh = smu;                          // [64][HSTR] half2, h<128
    u32* Eh = Qh + 64 * HSTR;               // [64][HSTR]
    float* Qa = (float*)(Eh + 64 * HSTR);   // [64][ASTR] e^{2Q}, h>=128
    float* Ea = Qa + 64 * ASTR;             // [64][ASTR]
    u32* vh = (u32*)(Ea + 64 * ASTR);       // [64] half2
    u64* vf = (u64*)(vh + 64);              // [64] f32x2

    const int tid = threadIdx.x;
    const int b = blockIdx.z, t0 = blockIdx.y << 6, n0 = blockIdx.x << 6;

    if (tid < 64) {
        float2 vv = ((const float2*)v)[tid];
        vh[tid] = packh2(vv.x, vv.y);
    } else if (tid < 128) {
        int k = tid - 64;
        ((float2*)vf)[k] = ((const float2*)v)[64 + k];
    }
    for (int i = tid; i < 1024; i += 256) {
        int row = i >> 4, c = i & 15;
        ((uint4*)&Qh[row * HSTR])[c] =
            ((const uint4*)(g_Qh + ((size_t)(t0 + row) * B_ + b) * 64))[c];
        ((uint4*)&Eh[row * HSTR])[c] =
            ((const uint4*)(g_Eh + ((size_t)b * N_ + n0 + row) * 64))[c];
    }
    for (int i = tid; i < 2048; i += 256) {
        int row = i >> 5, c = i & 31;
        ((uint4*)&Qa[row * ASTR])[c] =
            ((const uint4*)(g_Qa + ((size_t)(t0 + row) * B_ + b) * 128))[c];
        ((uint4*)&Ea[row * ASTR])[c] =
            ((const uint4*)(g_Ea + ((size_t)b * N_ + n0 + row) * 128))[c];
    }
    __syncthreads();

    const int tx = tid & 15, ty = tid >> 4;
    float acc[4][4];
#pragma unroll
    for (int i = 0; i < 4; i++)
#pragma unroll
        for (int jj = 0; jj < 4; jj++) acc[i][jj] = 0.f;

    // ---- phase 1: f16 MUFU path, h < 128 ----
    {
        const u32* qp = &Qh[ty * HSTR];
        const u32* ep = &Eh[tx * HSTR];
#pragma unroll 1
        for (int c = 0; c < 8; c++) {
            u32 hacc[4][4];
#pragma unroll
            for (int i = 0; i < 4; i++)
#pragma unroll
                for (int jj = 0; jj < 4; jj++) hacc[i][jj] = 0u;
#pragma unroll
            for (int s = 0; s < 2; s++) {
                const int o = (c * 2 + s) * 4;
                uint4 vv = *(const uint4*)&vh[o];
                uint4 q0 = *(const uint4*)(qp + o);
                uint4 q1 = *(const uint4*)(qp + 16 * HSTR + o);
                uint4 q2 = *(const uint4*)(qp + 32 * HSTR + o);
                uint4 q3 = *(const uint4*)(qp + 48 * HSTR + o);
                uint4 e0 = *(const uint4*)(ep + o);
                uint4 e1 = *(const uint4*)(ep + 16 * HSTR + o);
                uint4 e2 = *(const uint4*)(ep + 32 * HSTR + o);
                uint4 e3 = *(const uint4*)(ep + 48 * HSTR + o);
                AT4H(hacc[0][0], q0, e0, vv); AT4H(hacc[0][1], q0, e1, vv);
                AT4H(hacc[0][2], q0, e2, vv); AT4H(hacc[0][3], q0, e3, vv);
                AT4H(hacc[1][0], q1, e0, vv); AT4H(hacc[1][1], q1, e1, vv);
                AT4H(hacc[1][2], q1, e2, vv); AT4H(hacc[1][3], q1, e3, vv);
                AT4H(hacc[2][0], q2, e0, vv); AT4H(hacc[2][1], q2, e1, vv);
                AT4H(hacc[2][2], q2, e2, vv); AT4H(hacc[2][3], q2, e3, vv);
                AT4H(hacc[3][0], q3, e0, vv); AT4H(hacc[3][1], q3, e1, vv);
                AT4H(hacc[3][2], q3, e2, vv); AT4H(hacc[3][3], q3, e3, vv);
            }
#pragma unroll
            for (int i = 0; i < 4; i++)
#pragma unroll
                for (int jj = 0; jj < 4; jj++) {
                    u32 hb = hacc[i][jj];
                    acc[i][jj] += h2f_fast(hb) + h2f_fast(hb >> 16);
                }
        }
    }

    // ---- phase 2: exp/Newton FMA path, h >= 128 ----
    {
        const u64 ONES = fdup2(1.f), M2 = fdup2(-2.f), P2c = fdup2(2.f);
        const u64* bp = (const u64*)&Qa[ty * ASTR];
        const u64* ap = (const u64*)&Ea[tx * ASTR];
        u64 acc2[4][4];
#pragma unroll
        for (int i = 0; i < 4; i++)
#pragma unroll
            for (int jj = 0; jj < 4; jj++) acc2[i][jj] = 0ULL;

#pragma unroll 2
        for (int hp = 0; hp < 64; hp++) {
            u64 vv = vf[hp];
            u64 bb[4], aa[4];
            bb[0] = bp[hp];
            bb[1] = bp[hp + 16 * (ASTR / 2)];
            bb[2] = bp[hp + 32 * (ASTR / 2)];
            bb[3] = bp[hp + 48 * (ASTR / 2)];
            aa[0] = ap[hp];
            aa[1] = ap[hp + 16 * (ASTR / 2)];
            aa[2] = ap[hp + 32 * (ASTR / 2)];
            aa[3] = ap[hp + 48 * (ASTR / 2)];
#pragma unroll
            for (int i = 0; i < 4; i++)
#pragma unroll
                for (int jj = 0; jj < 4; jj++) {
                    u64 u = ffma2(aa[jj], bb[i], ONES);
                    u64 z2 = rcp_negz(u, M2, P2c);       // -1/u
                    acc2[i][jj] = ffma2(vv, z2, acc2[i][jj]);
                }
        }

        float vsum = 0.f;
#pragma unroll 8
        for (int k = 0; k < 64; k++) vsum += fsum2(vf[k]);
#pragma unroll
        for (int i = 0; i < 4; i++)
#pragma unroll
            for (int jj = 0; jj < 4; jj++)
                acc[i][jj] += vsum + 2.f * fsum2(acc2[i][jj]);
    }

#pragma unroll
    for (int i = 0; i < 4; i++) {
        float* op = out + ((size_t)b * T_ + t0 + ty + 16 * i) * N_ + n0 + tx;
#pragma unroll
        for (int jj = 0; jj < 4; jj++) op[16 * jj] = acc[i][jj];
    }
}

// ---------------------------------------------------------------------------
extern "C" void kernel_launch(void* const* d_in, const int* in_sizes, int n_in,
                              void* d_out, int out_size) {
    const float* enc   = (const float*)d_in[0];
    const float* W_ih  = (const float*)d_in[1];
    const float* W_hh  = (const float*)d_in[2];
    const float* b_ih  = (const float*)d_in[3];
    const float* b_hh  = (const float*)d_in[4];
    const float* W_ref = (const float*)d_in[5];
    const float* W_q   = (const float*)d_in[6];
    const float* v     = (const float*)d_in[7];
    float* out = (float*)d_out;

    cudaFuncSetAttribute(gemm_kernel, cudaFuncAttributeMaxDynamicSharedMemorySize, GEMM_SMEM);
    cudaFuncSetAttribute(scan_kernel, cudaFuncAttributeMaxDynamicSharedMemorySize, SCAN_SMEM);
    cudaFuncSetAttribute(attn_kernel, cudaFuncAttributeMaxDynamicSharedMemorySize, ATTN_SMEM);

    void *pEh, *pQh, *pEa, *pQa, *pHall;
    cudaGetSymbolAddress(&pEh, g_Eh);
    cudaGetSymbolAddress(&pQh, g_Qh);
    cudaGetSymbolAddress(&pEa, g_Ea);
    cudaGetSymbolAddress(&pQa, g_Qa);
    cudaGetSymbolAddress(&pHall, g_Hallh);

    gemm_kernel<<<dim3(2048, 2), 256, GEMM_SMEM>>>(
        enc, W_ref, (u32*)pEh, (float*)pEa, 0);
    scan_kernel<<<64, 512, SCAN_SMEM>>>(W_ih, W_hh, b_ih, b_hh);
    gemm_kernel<<<dim3(2048, 2), 256, GEMM_SMEM>>>(
        pHall, W_q, (u32*)pQh, (float*)pQa, 1);
    attn_kernel<<<dim3(8, 8, 256), 256, ATTN_SMEM>>>(v, out);
}

// round 17
// speedup vs baseline: 1.0417x; 1.0417x over previous
#include <cuda_runtime.h>
#include <cuda_fp16.h>
#include <math.h>

#define B_ 256
#define T_ 512
#define N_ 512
#define H_ 256

typedef unsigned long long u64;
typedef unsigned u32;

// ---------------- scratch (device globals; allocation-free) ----------------
__device__ u32   g_Eh[(size_t)B_ * N_ * 64];    // E half2, h<128   [b][n][h2]
__device__ u32   g_Qh[(size_t)T_ * B_ * 64];    // Q half2, h<128   [t][b][h2]
__device__ float g_Ea[(size_t)B_ * N_ * 128];   // e^{2E}, h>=128   [b][n][hc]
__device__ float g_Qa[(size_t)T_ * B_ * 128];   // e^{2Q}, h>=128   [t][b][hc]
__device__ u32   g_Hallh[(size_t)T_ * B_ * 128];// hiddens half2 [t][b][h2]
__device__ u32   g_hidh[2][B_ * 128];           // double-buffered hid half2
__device__ unsigned g_barcnt[32 * 32];          // 128B-padded barriers (32 grps)

// ---------------- fast-math helpers ----------------
__device__ __forceinline__ float tanha(float x) {
    float y; asm("tanh.approx.f32 %0, %1;" : "=f"(y) : "f"(x)); return y;
}
__device__ __forceinline__ float sigma_(float x) {
    return fmaf(0.5f, tanha(0.5f * x), 0.5f);
}
__device__ __forceinline__ u64 ffma2(u64 a, u64 b, u64 c) {
    u64 r; asm("fma.rn.f32x2 %0, %1, %2, %3;" : "=l"(r) : "l"(a), "l"(b), "l"(c));
    return r;
}
__device__ __forceinline__ u64 fmul2(u64 a, u64 b) {
    u64 r; asm("mul.rn.f32x2 %0, %1, %2;" : "=l"(r) : "l"(a), "l"(b));
    return r;
}
__device__ __forceinline__ u64 fdup2(float x) {
    u64 r; asm("mov.b64 %0, {%1, %1};" : "=l"(r) : "f"(x)); return r;
}
__device__ __forceinline__ float fsum2(u64 a) {
    float lo, hi; asm("mov.b64 {%0, %1}, %2;" : "=f"(lo), "=f"(hi) : "l"(a));
    return lo + hi;
}
__device__ __forceinline__ u32 packh2(float a, float b) {
    __half2 h = __floats2half2_rn(a, b);
    return *reinterpret_cast<u32*>(&h);
}
// half(low 16 bits) -> float, pure ALU (exact for normals)
__device__ __forceinline__ float h2f_fast(u32 hb) {
    u32 r = ((hb & 0x8000u) << 16) + ((hb & 0x7FFFu) << 13) + 0x38000000u;
    return __uint_as_float(r);
}
// packed Newton reciprocal: returns z2 = -1/u (rel err ~1e-5), u > 0 per lane
__device__ __forceinline__ u64 rcp_negz(u64 u, u64 M2, u64 P2c) {
    u32 lo, hi;
    asm("mov.b64 {%0, %1}, %2;" : "=r"(lo), "=r"(hi) : "l"(u));
    lo = 0x7EF127EAu - lo;
    hi = 0x7EF127EAu - hi;
    u64 y0;
    asm("mov.b64 %0, {%1, %2};" : "=l"(y0) : "r"(lo), "r"(hi));
    u64 t1 = ffma2(u, y0, M2);   // u*y0 - 2
    u64 z1 = fmul2(y0, t1);      // -y1
    u64 t2 = ffma2(u, z1, P2c);  // 2 + u*z1
    return fmul2(z1, t2);        // -y2  (y2 ~= 1/u)
}
__device__ __forceinline__ u32 smem_u32(const void* p) {
    u32 a;
    asm("{ .reg .u64 t; cvta.to.shared.u64 t, %1; cvt.u32.u64 %0, t; }"
        : "=r"(a) : "l"(p));
    return a;
}

#define LDSM4(a, addr)                                                   \
    asm volatile("ldmatrix.sync.aligned.m8n8.x4.shared.b16 "             \
                 "{%0,%1,%2,%3}, [%4];"                                  \
                 : "=r"((a)[0]), "=r"((a)[1]), "=r"((a)[2]), "=r"((a)[3])\
                 : "r"(addr))

#define MMA16816(d, a, b0, b1)                                           \
    asm volatile("mma.sync.aligned.m16n8k16.row.col.f32.f16.f16.f32 "    \
                 "{%0,%1,%2,%3}, {%4,%5,%6,%7}, {%8,%9}, {%0,%1,%2,%3};" \
                 : "+f"((d)[0]), "+f"((d)[1]), "+f"((d)[2]), "+f"((d)[3])\
                 : "r"((a)[0]), "r"((a)[1]), "r"((a)[2]), "r"((a)[3]),   \
                   "r"(b0), "r"(b1))

// ---------------------------------------------------------------------------
// Tensor-core GEMM (R12, proven): Out[m][k] = sum_h X[m][h] * W[k][h]
// Block (0,0,0) zeroes scan barrier counters.
// ---------------------------------------------------------------------------
#define GXP 264
#define GWP 264
#define GEMM_SMEM (64 * GXP * 2 + 128 * GWP * 2)

__global__ __launch_bounds__(256) void gemm_kernel(
    const void* __restrict__ Xin, const float* __restrict__ W,
    u32* __restrict__ OutH, float* __restrict__ OutA, int xf16) {
    extern __shared__ char gsm[];
    __half* Xh = (__half*)gsm;          // [64][GXP]
    __half* Wh = Xh + 64 * GXP;         // [128][GWP]
    const int tid = threadIdx.x;
    if (blockIdx.x == 0 && blockIdx.y == 0 && tid < 32) g_barcnt[tid * 32] = 0u;

    const size_t m0 = (size_t)blockIdx.x * 64;
    const int k0 = blockIdx.y * 128;

    if (xf16) {
        const uint4* xp = (const uint4*)((const __half*)Xin + m0 * H_);
        for (int i = tid; i < 2048; i += 256) {
            uint4 v = __ldg(xp + i);
            int row = i >> 5, c8 = i & 31;
            u32* d = (u32*)Xh + row * (GXP / 2) + c8 * 4;
            d[0] = v.x; d[1] = v.y; d[2] = v.z; d[3] = v.w;
        }
    } else {
        const float4* xp = (const float4*)((const float*)Xin + m0 * H_);
        for (int i = tid; i < 4096; i += 256) {
            float4 v = __ldg(xp + i);
            int row = i >> 6, c4 = i & 63;
            u32* d = (u32*)Xh + row * (GXP / 2) + c4 * 2;
            d[0] = packh2(v.x, v.y);
            d[1] = packh2(v.z, v.w);
        }
    }
    {
        const float4* wp = (const float4*)(W + (size_t)k0 * H_);
        for (int i = tid; i < 8192; i += 256) {
            float4 v = __ldg(wp + i);
            int row = i >> 6, c4 = i & 63;
            u32* d = (u32*)Wh + row * (GWP / 2) + c4 * 2;
            d[0] = packh2(v.x, v.y);
            d[1] = packh2(v.z, v.w);
        }
    }
    __syncthreads();

    const int w = tid >> 5, lane = tid & 31;
    u32 breg[16][2][2];
#pragma unroll
    for (int kk = 0; kk < 16; kk++)
#pragma unroll
        for (int nn = 0; nn < 2; nn++) {
            int row = w * 16 + nn * 8 + (lane >> 2);
            int h0 = kk * 16 + (lane & 3) * 2;
            breg[kk][nn][0] = *(const u32*)&Wh[row * GWP + h0];
            breg[kk][nn][1] = *(const u32*)&Wh[row * GWP + h0 + 8];
        }

    const u32 ldb = smem_u32(Xh) +
                    (u32)(((lane & 15) * GXP + ((lane >> 4) << 3)) * 2);
    float c[4][2][4];
#pragma unroll
    for (int mi = 0; mi < 4; mi++)
#pragma unroll
        for (int nn = 0; nn < 2; nn++)
#pragma unroll
            for (int q = 0; q < 4; q++) c[mi][nn][q] = 0.f;

#pragma unroll
    for (int kk = 0; kk < 16; kk++) {
#pragma unroll
        for (int mi = 0; mi < 4; mi++) {
            u32 a[4];
            LDSM4(a, ldb + (u32)((mi * 16 * GXP + kk * 16) * 2));
            MMA16816(c[mi][0], a, breg[kk][0][0], breg[kk][0][1]);
            MMA16816(c[mi][1], a, breg[kk][1][0], breg[kk][1][1]);
        }
    }

    const int qr = lane >> 2, qc = (lane & 3) * 2;
    if (k0 == 0) {
#pragma unroll
        for (int mi = 0; mi < 4; mi++)
#pragma unroll
            for (int nn = 0; nn < 2; nn++) {
                size_t m = m0 + mi * 16 + qr;
                int widx = w * 8 + nn * 4 + (lane & 3);
                OutH[m * 64 + widx] = packh2(c[mi][nn][0], c[mi][nn][1]);
                OutH[(m + 8) * 64 + widx] = packh2(c[mi][nn][2], c[mi][nn][3]);
            }
    } else {
#pragma unroll
        for (int mi = 0; mi < 4; mi++)
#pragma unroll
            for (int nn = 0; nn < 2; nn++) {
                size_t m = m0 + mi * 16 + qr;
                int col = w * 16 + nn * 8 + qc;
                *(float2*)&OutA[m * 128 + col] =
                    make_float2(__expf(2.f * c[mi][nn][0]),
                                __expf(2.f * c[mi][nn][1]));
                *(float2*)&OutA[(m + 8) * 128 + col] =
                    make_float2(__expf(2.f * c[mi][nn][2]),
                                __expf(2.f * c[mi][nn][3]));
            }
    }
}

// ---------------------------------------------------------------------------
// LSTM scan, 2 groups/SM: 32 groups x 8 CTAs (256 CTAs, 2/SM), 256 threads.
// Group owns 8 batch rows; CTA j owns 32 gate-h-cols (weights 128x256 fp16,
// 68KB, smem-resident; ~81KB total -> 2 CTAs/SM). Co-resident CTAs belong to
// INDEPENDENT groups -> their compute hides each other's barrier/reload
// latency. MMA m16 pads 8 zero rows (hidh rows 8-15 pinned at zero).
// ---------------------------------------------------------------------------
#define WPAD 264
#define HPAD 264
#define PST 132
#define SCAN_SMEM (128 * WPAD * 2 + 16 * HPAD * 2 + 8 * PST * 4 + 128 * 4)

__global__ __launch_bounds__(256) void scan_kernel(
    const float* __restrict__ W_ih, const float* __restrict__ W_hh,
    const float* __restrict__ b_ih, const float* __restrict__ b_hh) {
    extern __shared__ char smc[];
    __half* Wh  = (__half*)smc;                    // [128][WPAD] fp16 weights
    __half* hidh = Wh + 128 * WPAD;                // [16][HPAD] (rows 8-15 = 0)
    float* P   = (float*)(hidh + 16 * HPAD);       // [8][PST] gates f32
    float* bcs = P + 8 * PST;                      // [128]

    const int tid = threadIdx.x;
    const int grp = blockIdx.x >> 3, j = blockIdx.x & 7;   // 32 groups
    const int r0 = grp * 8, hbase = j * 32;
    const int w = tid >> 5, lane = tid & 31;

    // ---- load combined weights as fp16 (identical slice layout to R15) ----
    for (int idx = tid; idx < 128 * 256; idx += 256) {
        int q = idx >> 8, h = idx & 255;              // q = gt*32 + hcol
        int row = (q >> 5) * 256 + hbase + (q & 31);
        size_t ww = (size_t)row * H_ + h;
        Wh[q * WPAD + h] = __float2half(W_ih[ww] + W_hh[ww]);
    }
    if (tid < 128) {
        int row = (tid >> 5) * 256 + hbase + (tid & 31);
        bcs[tid] = b_ih[row] + b_hh[row];
    }
    // hid: all 16 rows zero (rows 8-15 stay zero forever)
    for (int i2 = tid; i2 < 16 * (HPAD / 2); i2 += 256)
        ((u32*)hidh)[i2] = 0u;
    const int hc2 = tid & 15, bat = tid >> 4;   // update: tid<128 -> bat 0..7
    float cell[2] = {0.f, 0.f};
    __syncthreads();

    // ---- hoist stationary B fragments (identical to R15) ----
    u32 breg[16][2][2];
#pragma unroll
    for (int kk = 0; kk < 16; kk++)
#pragma unroll
        for (int nn = 0; nn < 2; nn++) {
            int row = w * 16 + nn * 8 + (lane >> 2);
            int h0 = kk * 16 + (lane & 3) * 2;
            breg[kk][nn][0] = *(const u32*)&Wh[row * WPAD + h0];
            breg[kk][nn][1] = *(const u32*)&Wh[row * WPAD + h0 + 8];
        }

    const u32 ld_base = smem_u32(hidh) +
                        (u32)(((lane & 15) * HPAD + ((lane >> 4) << 3)) * 2);
    const int qr = lane >> 2, qc = (lane & 3) * 2;
    unsigned* barp = &g_barcnt[grp * 32];

    for (int t = 0; t < T_; t++) {
        float c0[4] = {0.f, 0.f, 0.f, 0.f};
        float c1[4] = {0.f, 0.f, 0.f, 0.f};
#pragma unroll
        for (int kk = 0; kk < 16; kk++) {
            u32 a[4];
            LDSM4(a, ld_base + (u32)(kk * 32));
            MMA16816(c0, a, breg[kk][0][0], breg[kk][0][1]);
            MMA16816(c1, a, breg[kk][1][0], breg[kk][1][1]);
        }
        // scatter only valid rows (qr = 0..7); rows qr+8 are zero-padding
        {
            int col = w * 16 + qc;
            *(float2*)&P[qr * PST + col] = make_float2(c0[0], c0[1]);
            *(float2*)&P[qr * PST + col + 8] = make_float2(c1[0], c1[1]);
        }
        __syncthreads();

        // ---- LSTM update: tid<128 -> bat(0..7) x cols (2hc2, 2hc2+1) ----
        const int buf = (t + 1) & 1;
        if (tid < 128) {
            const float* pp = &P[bat * PST];
            float2 iv = *(const float2*)&pp[2 * hc2];
            float2 fv = *(const float2*)&pp[32 + 2 * hc2];
            float2 gv = *(const float2*)&pp[64 + 2 * hc2];
            float2 ov = *(const float2*)&pp[96 + 2 * hc2];
            float2 bi = *(const float2*)&bcs[2 * hc2];
            float2 bf = *(const float2*)&bcs[32 + 2 * hc2];
            float2 bg = *(const float2*)&bcs[64 + 2 * hc2];
            float2 bo = *(const float2*)&bcs[96 + 2 * hc2];
            cell[0] = sigma_(fv.x + bf.x) * cell[0] +
                      sigma_(iv.x + bi.x) * tanha(gv.x + bg.x);
            cell[1] = sigma_(fv.y + bf.y) * cell[1] +
                      sigma_(iv.y + bi.y) * tanha(gv.y + bg.y);
            float hd0 = sigma_(ov.x + bo.x) * tanha(cell[0]);
            float hd1 = sigma_(ov.y + bo.y) * tanha(cell[1]);
            u32 h2 = packh2(hd0, hd1);
            g_hidh[buf][(r0 + bat) * 128 + (hbase >> 1) + hc2] = h2;
            g_Hallh[((size_t)t * B_ + r0 + bat) * 128 + (hbase >> 1) + hc2] = h2;
        }

        // ---- group barrier (8 CTAs): release arrive, acquire poll ----
        __syncthreads();
        if (tid == 0) {
            asm volatile("red.release.gpu.global.add.u32 [%0], %1;"
                         :: "l"(barp), "r"(1u) : "memory");
            unsigned tgt = (unsigned)(t + 1) * 8u, cur;
            do {
                asm volatile("ld.acquire.gpu.global.u32 %0, [%1];"
                             : "=r"(cur) : "l"(barp) : "memory");
            } while (cur < tgt);
        }
        __syncthreads();

        // ---- reload group's 8 hid rows (256 uint4 = 1/thread) ----
        {
            const uint4* src = (const uint4*)&g_hidh[buf][r0 * 128];
            uint4 v = __ldcg(src + tid);
            int bb = tid >> 5, c8 = tid & 31;
            u32* d = (u32*)hidh + bb * (HPAD / 2) + c8 * 4;
            d[0] = v.x; d[1] = v.y; d[2] = v.z; d[3] = v.w;
        }
        __syncthreads();
    }
}

// ---------------------------------------------------------------------------
// Attention hybrid (R12 form, proven fastest — FROZEN):
//   phase 1 (h<128):  HADD2 -> tanh.f16x2 (MUFU) -> HFMA2 -> ALU widen
//   phase 2 (h>=128): tanh = 1 - 2/(1+ab), Newton rcp on FMA pipe
// ---------------------------------------------------------------------------
#define HSTR 68
#define ASTR 132
#define ATTN_SMEM (2 * 64 * HSTR * 4 + 2 * 64 * ASTR * 4 + 64 * 4 + 64 * 8)

#define HADD2A(r, a, b) asm("add.rn.f16x2 %0, %1, %2;" : "=r"(r) : "r"(a), "r"(b))
#define TANH2A(r, a)    asm("tanh.approx.f16x2 %0, %1;" : "=r"(r) : "r"(a))
#define HFMA2A(d, a, b) asm("fma.rn.f16x2 %0, %1, %2, %3;" : "=r"(d) : "r"(a), "r"(b), "r"(d))

#define ATC(accr, qc, ec, vc)            \
    { u32 s_, t_;                        \
      HADD2A(s_, (qc), (ec));            \
      TANH2A(t_, s_);                    \
      HFMA2A((accr), (vc), t_); }

#define AT4H(accr, q4, e4, v4)           \
    ATC(accr, (q4).x, (e4).x, (v4).x);   \
    ATC(accr, (q4).y, (e4).y, (v4).y);   \
    ATC(accr, (q4).z, (e4).z, (v4).z);   \
    ATC(accr, (q4).w, (e4).w, (v4).w)

__global__ __launch_bounds__(256) void attn_kernel(
    const float* __restrict__ v, float* __restrict__ out) {
    extern __shared__ u32 smu[];
    u32* Qh = smu;                          // [64][HSTR] half2, h<128
    u32* Eh = Qh + 64 * HSTR;               // [64][HSTR]
    float* Qa = (float*)(Eh + 64 * HSTR);   // [64][ASTR] e^{2Q}, h>=128
    float* Ea = Qa + 64 * ASTR;             // [64][ASTR]
    u32* vh = (u32*)(Ea + 64 * ASTR);       // [64] half2
    u64* vf = (u64*)(vh + 64);              // [64] f32x2

    const int tid = threadIdx.x;
    const int b = blockIdx.z, t0 = blockIdx.y << 6, n0 = blockIdx.x << 6;

    if (tid < 64) {
        float2 vv = ((const float2*)v)[tid];
        vh[tid] = packh2(vv.x, vv.y);
    } else if (tid < 128) {
        int k = tid - 64;
        ((float2*)vf)[k] = ((const float2*)v)[64 + k];
    }
    for (int i = tid; i < 1024; i += 256) {
        int row = i >> 4, c = i & 15;
        ((uint4*)&Qh[row * HSTR])[c] =
            ((const uint4*)(g_Qh + ((size_t)(t0 + row) * B_ + b) * 64))[c];
        ((uint4*)&Eh[row * HSTR])[c] =
            ((const uint4*)(g_Eh + ((size_t)b * N_ + n0 + row) * 64))[c];
    }
    for (int i = tid; i < 2048; i += 256) {
        int row = i >> 5, c = i & 31;
        ((uint4*)&Qa[row * ASTR])[c] =
            ((const uint4*)(g_Qa + ((size_t)(t0 + row) * B_ + b) * 128))[c];
        ((uint4*)&Ea[row * ASTR])[c] =
            ((const uint4*)(g_Ea + ((size_t)b * N_ + n0 + row) * 128))[c];
    }
    __syncthreads();

    const int tx = tid & 15, ty = tid >> 4;
    float acc[4][4];
#pragma unroll
    for (int i = 0; i < 4; i++)
#pragma unroll
        for (int jj = 0; jj < 4; jj++) acc[i][jj] = 0.f;

    // ---- phase 1: f16 MUFU path, h < 128 ----
    {
        const u32* qp = &Qh[ty * HSTR];
        const u32* ep = &Eh[tx * HSTR];
#pragma unroll 1
        for (int c = 0; c < 8; c++) {
            u32 hacc[4][4];
#pragma unroll
            for (int i = 0; i < 4; i++)
#pragma unroll
                for (int jj = 0; jj < 4; jj++) hacc[i][jj] = 0u;
#pragma unroll
            for (int s = 0; s < 2; s++) {
                const int o = (c * 2 + s) * 4;
                uint4 vv = *(const uint4*)&vh[o];
                uint4 q0 = *(const uint4*)(qp + o);
                uint4 q1 = *(const uint4*)(qp + 16 * HSTR + o);
                uint4 q2 = *(const uint4*)(qp + 32 * HSTR + o);
                uint4 q3 = *(const uint4*)(qp + 48 * HSTR + o);
                uint4 e0 = *(const uint4*)(ep + o);
                uint4 e1 = *(const uint4*)(ep + 16 * HSTR + o);
                uint4 e2 = *(const uint4*)(ep + 32 * HSTR + o);
                uint4 e3 = *(const uint4*)(ep + 48 * HSTR + o);
                AT4H(hacc[0][0], q0, e0, vv); AT4H(hacc[0][1], q0, e1, vv);
                AT4H(hacc[0][2], q0, e2, vv); AT4H(hacc[0][3], q0, e3, vv);
                AT4H(hacc[1][0], q1, e0, vv); AT4H(hacc[1][1], q1, e1, vv);
                AT4H(hacc[1][2], q1, e2, vv); AT4H(hacc[1][3], q1, e3, vv);
                AT4H(hacc[2][0], q2, e0, vv); AT4H(hacc[2][1], q2, e1, vv);
                AT4H(hacc[2][2], q2, e2, vv); AT4H(hacc[2][3], q2, e3, vv);
                AT4H(hacc[3][0], q3, e0, vv); AT4H(hacc[3][1], q3, e1, vv);
                AT4H(hacc[3][2], q3, e2, vv); AT4H(hacc[3][3], q3, e3, vv);
            }
#pragma unroll
            for (int i = 0; i < 4; i++)
#pragma unroll
                for (int jj = 0; jj < 4; jj++) {
                    u32 hb = hacc[i][jj];
                    acc[i][jj] += h2f_fast(hb) + h2f_fast(hb >> 16);
                }
        }
    }

    // ---- phase 2: exp/Newton FMA path, h >= 128 ----
    {
        const u64 ONES = fdup2(1.f), M2 = fdup2(-2.f), P2c = fdup2(2.f);
        const u64* bp = (const u64*)&Qa[ty * ASTR];
        const u64* ap = (const u64*)&Ea[tx * ASTR];
        u64 acc2[4][4];
#pragma unroll
        for (int i = 0; i < 4; i++)
#pragma unroll
            for (int jj = 0; jj < 4; jj++) acc2[i][jj] = 0ULL;

#pragma unroll 2
        for (int hp = 0; hp < 64; hp++) {
            u64 vv = vf[hp];
            u64 bb[4], aa[4];
            bb[0] = bp[hp];
            bb[1] = bp[hp + 16 * (ASTR / 2)];
            bb[2] = bp[hp + 32 * (ASTR / 2)];
            bb[3] = bp[hp + 48 * (ASTR / 2)];
            aa[0] = ap[hp];
            aa[1] = ap[hp + 16 * (ASTR / 2)];
            aa[2] = ap[hp + 32 * (ASTR / 2)];
            aa[3] = ap[hp + 48 * (ASTR / 2)];
#pragma unroll
            for (int i = 0; i < 4; i++)
#pragma unroll
                for (int jj = 0; jj < 4; jj++) {
                    u64 u = ffma2(aa[jj], bb[i], ONES);
                    u64 z2 = rcp_negz(u, M2, P2c);       // -1/u
                    acc2[i][jj] = ffma2(vv, z2, acc2[i][jj]);
                }
        }

        float vsum = 0.f;
#pragma unroll 8
        for (int k = 0; k < 64; k++) vsum += fsum2(vf[k]);
#pragma unroll
        for (int i = 0; i < 4; i++)
#pragma unroll
            for (int jj = 0; jj < 4; jj++)
                acc[i][jj] += vsum + 2.f * fsum2(acc2[i][jj]);
    }

#pragma unroll
    for (int i = 0; i < 4; i++) {
        float* op = out + ((size_t)b * T_ + t0 + ty + 16 * i) * N_ + n0 + tx;
#pragma unroll
        for (int jj = 0; jj < 4; jj++) op[16 * jj] = acc[i][jj];
    }
}

// ---------------------------------------------------------------------------
extern "C" void kernel_launch(void* const* d_in, const int* in_sizes, int n_in,
                              void* d_out, int out_size) {
    const float* enc   = (const float*)d_in[0];
    const float* W_ih  = (const float*)d_in[1];
    const float* W_hh  = (const float*)d_in[2];
    const float* b_ih  = (const float*)d_in[3];
    const float* b_hh  = (const float*)d_in[4];
    const float* W_ref = (const float*)d_in[5];
    const float* W_q   = (const float*)d_in[6];
    const float* v     = (const float*)d_in[7];
    float* out = (float*)d_out;

    cudaFuncSetAttribute(gemm_kernel, cudaFuncAttributeMaxDynamicSharedMemorySize, GEMM_SMEM);
    cudaFuncSetAttribute(scan_kernel, cudaFuncAttributeMaxDynamicSharedMemorySize, SCAN_SMEM);
    cudaFuncSetAttribute(attn_kernel, cudaFuncAttributeMaxDynamicSharedMemorySize, ATTN_SMEM);

    void *pEh, *pQh, *pEa, *pQa, *pHall;
    cudaGetSymbolAddress(&pEh, g_Eh);
    cudaGetSymbolAddress(&pQh, g_Qh);
    cudaGetSymbolAddress(&pEa, g_Ea);
    cudaGetSymbolAddress(&pQa, g_Qa);
    cudaGetSymbolAddress(&pHall, g_Hallh);

    gemm_kernel<<<dim3(2048, 2), 256, GEMM_SMEM>>>(
        enc, W_ref, (u32*)pEh, (float*)pEa, 0);
    scan_kernel<<<256, 256, SCAN_SMEM>>>(W_ih, W_hh, b_ih, b_hh);
    gemm_kernel<<<dim3(2048, 2), 256, GEMM_SMEM>>>(
        pHall, W_q, (u32*)pQh, (float*)pQa, 1);
    attn_kernel<<<dim3(8, 8, 256), 256, ATTN_SMEM>>>(v, out);
}